// round 15
// baseline (speedup 1.0000x reference)
#include <cuda_runtime.h>
#include <cuda_fp16.h>
#include <stdint.h>

// Problem constants
#define NUM_STEPS 25
#define BATCH     4096
#define NIN       784
#define NHID      1000
#define NOUT      10
#define MTOT      (NUM_STEPS * BATCH)   // 102400
#define BETA      0.95f
#define THRESH    1.0f

// Flag window per step (validated round 13).
#define DELTA 5e-5f

// Scratch (device globals; no runtime allocation allowed)
__device__ float     g_cur1[(size_t)MTOT * NHID];
__device__ uint32_t  g_maskT[(size_t)32 * MTOT];    // spk1 bits, [word][t*B+b]
__device__ float     g_cur2[(size_t)MTOT * NOUT];
__device__ uint32_t  g_flag[BATCH * 32];
__device__ __half    g_xh[(size_t)MTOT * NIN];
__device__ __half    g_xl[(size_t)MTOT * NIN];
__device__ __half    g_wh[(size_t)1024 * NIN];
__device__ __half    g_wl[(size_t)1024 * NIN];

static __device__ __forceinline__ uint32_t smem_u32(const void* p) {
    uint32_t a;
    asm("{ .reg .u64 t; cvta.to.shared.u64 t, %1; cvt.u32.u64 %0, t; }"
        : "=r"(a) : "l"(p));
    return a;
}

#define LDMX4(r0, r1, r2, r3, a) \
    asm volatile("ldmatrix.sync.aligned.m8n8.x4.shared.b16 {%0,%1,%2,%3}, [%4];" \
                 : "=r"(r0), "=r"(r1), "=r"(r2), "=r"(r3) : "r"(a))

#define MMA_F16(c, a, b) \
    asm volatile("mma.sync.aligned.m16n8k16.row.col.f32.f16.f16.f32 " \
                 "{%0,%1,%2,%3}, {%4,%5,%6,%7}, {%8,%9}, {%0,%1,%2,%3};" \
                 : "+f"((c)[0]), "+f"((c)[1]), "+f"((c)[2]), "+f"((c)[3]) \
                 : "r"((a)[0]), "r"((a)[1]), "r"((a)[2]), "r"((a)[3]), \
                   "r"((b)[0]), "r"((b)[1]))

#define CP_ASYNC_CG(dst, src) \
    asm volatile("cp.async.cg.shared.global [%0], [%1], 16;" \
                 :: "r"(dst), "l"(src) : "memory")
#define CP_COMMIT() asm volatile("cp.async.commit_group;" ::: "memory")
// Wait until at most 1 group pending -> the OLDEST pending stage has landed.
#define CP_WAIT1()  asm volatile("cp.async.wait_group 1;" ::: "memory")

// ---------------------------------------------------------------------------
// Split kernels (vectorized): v = vh + vl (fp16 hi + fp16 residual).
// ---------------------------------------------------------------------------
__global__ void __launch_bounds__(256)
splitx_kernel(const float* __restrict__ X)
{
    const int id = blockIdx.x * 256 + threadIdx.x;   // < MTOT*196
    const int m  = id / 196;
    const int k  = (id - m * 196) * 4;
    const float4 v = *(const float4*)(X + (size_t)m * NIN + k);
    __half h0 = __float2half_rn(v.x), h1 = __float2half_rn(v.y);
    __half h2 = __float2half_rn(v.z), h3 = __float2half_rn(v.w);
    __half l0 = __float2half_rn(v.x - __half2float(h0));
    __half l1 = __float2half_rn(v.y - __half2float(h1));
    __half l2 = __float2half_rn(v.z - __half2float(h2));
    __half l3 = __float2half_rn(v.w - __half2float(h3));
    __half2 hh[2] = {__halves2half2(h0, h1), __halves2half2(h2, h3)};
    __half2 ll[2] = {__halves2half2(l0, l1), __halves2half2(l2, l3)};
    *(uint2*)(g_xh + (size_t)m * NIN + k) = *(uint2*)hh;
    *(uint2*)(g_xl + (size_t)m * NIN + k) = *(uint2*)ll;
}

__global__ void __launch_bounds__(256)
splitw_kernel(const float* __restrict__ W1)
{
    const int id = blockIdx.x * 256 + threadIdx.x;   // < 1024*196
    const int h  = id / 196;
    const int k  = (id - h * 196) * 4;
    float4 v = make_float4(0.f, 0.f, 0.f, 0.f);
    if (h < NHID) v = *(const float4*)(W1 + (size_t)h * NIN + k);
    __half h0 = __float2half_rn(v.x), h1 = __float2half_rn(v.y);
    __half h2 = __float2half_rn(v.z), h3 = __float2half_rn(v.w);
    __half l0 = __float2half_rn(v.x - __half2float(h0));
    __half l1 = __float2half_rn(v.y - __half2float(h1));
    __half l2 = __float2half_rn(v.z - __half2float(h2));
    __half l3 = __float2half_rn(v.w - __half2float(h3));
    __half2 hh[2] = {__halves2half2(h0, h1), __halves2half2(h2, h3)};
    __half2 ll[2] = {__halves2half2(l0, l1), __halves2half2(l2, l3)};
    *(uint2*)(g_wh + (size_t)h * NIN + k) = *(uint2*)hh;
    *(uint2*)(g_wl + (size_t)h * NIN + k) = *(uint2*)ll;
}

// ---------------------------------------------------------------------------
// gemm1 on HMMA fp16: cur1 ~= Xh@Wh^T + Xh@Wl^T + Xl@Wh^T + b1.
// CTA tile 128x128, 8 warps (2x4), warp tile 64x32, K in 49 steps of 16.
// 3-stage cp.async pipeline; per stage 4 tiles (Ah, Al, Bh, Bl), 128 x 48B.
// ---------------------------------------------------------------------------
#define TILE_BYTES 6144        // 128 * 48
#define STAGE_BYTES 24576
#define NKS 49
#define STAGES 3

__global__ void __launch_bounds__(256)
gemm1t_kernel(const float* __restrict__ b1)
{
    extern __shared__ __align__(16) char smem[];   // STAGES * STAGE_BYTES

    const int tid    = threadIdx.x;
    const int wid    = tid >> 5;
    const int lane   = tid & 31;
    const int bm     = blockIdx.y * 128;
    const int bn     = blockIdx.x * 128;
    const int warp_m = (wid >> 2) * 64;
    const int warp_n = (wid & 3) * 32;

    const int lrow = tid >> 1;
    const int lc   = tid & 1;
    const __half* gxh = g_xh + (size_t)(bm + lrow) * NIN + lc * 8;
    const __half* gxl = g_xl + (size_t)(bm + lrow) * NIN + lc * 8;
    const __half* gwh = g_wh + (size_t)(bn + lrow) * NIN + lc * 8;
    const __half* gwl = g_wl + (size_t)(bn + lrow) * NIN + lc * 8;
    const uint32_t soff = (uint32_t)(lrow * 48 + lc * 16);

    const uint32_t sb = smem_u32(smem);
    const uint32_t aoff = (uint32_t)((warp_m + (lane & 15)) * 48 + (lane >> 4) * 16);
    const uint32_t boff0 = (uint32_t)((warp_n + ((lane >> 4) << 3) + (lane & 7)) * 48
                                      + ((lane >> 3) & 1) * 16);
    const uint32_t boff1 = boff0 + 16 * 48;

    float acc[4][4][4];
#pragma unroll
    for (int i = 0; i < 4; i++)
#pragma unroll
        for (int j = 0; j < 4; j++)
#pragma unroll
            for (int r = 0; r < 4; r++) acc[i][j][r] = 0.f;

#define ISSUE(kt) do { \
        const uint32_t s_ = sb + (uint32_t)((kt) % STAGES) * STAGE_BYTES + soff; \
        const int ko_ = (kt) * 16; \
        CP_ASYNC_CG(s_,                  gxh + ko_); \
        CP_ASYNC_CG(s_ + TILE_BYTES,     gxl + ko_); \
        CP_ASYNC_CG(s_ + 2 * TILE_BYTES, gwh + ko_); \
        CP_ASYNC_CG(s_ + 3 * TILE_BYTES, gwl + ko_); \
    } while (0)

    ISSUE(0); CP_COMMIT();
    ISSUE(1); CP_COMMIT();

#pragma unroll 1
    for (int kt = 0; kt < NKS; kt++) {
        CP_WAIT1();            // oldest pending group (stage kt) has landed
        __syncthreads();       // all warps done with stage kt-1's reads
        if (kt + 2 < NKS) ISSUE(kt + 2);
        CP_COMMIT();

        const uint32_t st = sb + (uint32_t)(kt % STAGES) * STAGE_BYTES;

        uint32_t bh[8], bl[8];
        LDMX4(bh[0], bh[1], bh[2], bh[3], st + 2 * TILE_BYTES + boff0);
        LDMX4(bh[4], bh[5], bh[6], bh[7], st + 2 * TILE_BYTES + boff1);
        LDMX4(bl[0], bl[1], bl[2], bl[3], st + 3 * TILE_BYTES + boff0);
        LDMX4(bl[4], bl[5], bl[6], bl[7], st + 3 * TILE_BYTES + boff1);

#pragma unroll
        for (int mi = 0; mi < 4; mi++) {
            uint32_t ah[4], al[4];
            LDMX4(ah[0], ah[1], ah[2], ah[3], st + aoff + mi * (16 * 48));
            LDMX4(al[0], al[1], al[2], al[3], st + TILE_BYTES + aoff + mi * (16 * 48));
#pragma unroll
            for (int nj = 0; nj < 4; nj++) {
                uint32_t bhf[2] = {bh[nj * 2], bh[nj * 2 + 1]};
                uint32_t blf[2] = {bl[nj * 2], bl[nj * 2 + 1]};
                MMA_F16(acc[mi][nj], ah, bhf);   // hh
                MMA_F16(acc[mi][nj], ah, blf);   // hl
                MMA_F16(acc[mi][nj], al, bhf);   // lh
            }
        }
    }
#undef ISSUE

    const int m0 = bm + warp_m + (lane >> 2);
    const int n0 = bn + warp_n + (lane & 3) * 2;
#pragma unroll
    for (int mi = 0; mi < 4; mi++) {
#pragma unroll
        for (int nj = 0; nj < 4; nj++) {
            const int n = n0 + nj * 8;
            if (n < NHID - 1) {
                const float bx = __ldg(&b1[n]);
                const float by = __ldg(&b1[n + 1]);
                const int mA = m0 + mi * 16;
                float2 v0, v1;
                v0.x = __fadd_rn(acc[mi][nj][0], bx);
                v0.y = __fadd_rn(acc[mi][nj][1], by);
                v1.x = __fadd_rn(acc[mi][nj][2], bx);
                v1.y = __fadd_rn(acc[mi][nj][3], by);
                *(float2*)&g_cur1[(size_t)mA * NHID + n] = v0;
                *(float2*)&g_cur1[(size_t)(mA + 8) * NHID + n] = v1;
            }
        }
    }
}

// ---------------------------------------------------------------------------
// flagrec: preload all 25 cur1 values (MLP=25), then recurrence with error
// radius; writes provisional spike mask + per-chain flag bits.
// ---------------------------------------------------------------------------
__global__ void __launch_bounds__(256)
flagrec_kernel()
{
    const int warp  = (blockIdx.x * blockDim.x + threadIdx.x) >> 5;
    const int lane  = threadIdx.x & 31;
    const int chunk = warp & 31;
    const int b     = warp >> 5;
    if (b >= BATCH) return;

    const int h = chunk * 32 + lane;
    const bool valid = (h < NHID);

    float cbuf[NUM_STEPS];
#pragma unroll
    for (int t = 0; t < NUM_STEPS; t++)
        cbuf[t] = valid ? g_cur1[((size_t)t * BATCH + b) * NHID + h] : -1.f;

    float mem = 0.f, e = 0.f;
    bool flg = false;
#pragma unroll
    for (int t = 0; t < NUM_STEPS; t++) {
        const float c = cbuf[t];
        const float rst = (mem > THRESH) ? THRESH : 0.f;
        mem = __fsub_rn(__fadd_rn(__fmul_rn(BETA, mem), c), rst);
        e = BETA * e + DELTA + 2e-7f * (fabsf(mem) + 2.f);
        flg = flg || (valid && fabsf(mem - THRESH) <= e);
        const uint32_t w = __ballot_sync(0xffffffffu, mem > THRESH);
        if (lane == 0)
            g_maskT[(size_t)chunk * MTOT + (size_t)t * BATCH + b] = w;
    }
    const uint32_t f = __ballot_sync(0xffffffffu, flg);
    if (lane == 0) g_flag[b * 32 + chunk] = f;
}

// ---------------------------------------------------------------------------
// Fixup: exact unfused chain for flagged (b,h); patch mask bits atomically.
// ---------------------------------------------------------------------------
#define XLD 785

__global__ void __launch_bounds__(256)
fixup_kernel(const float* __restrict__ X, const float* __restrict__ W1,
             const float* __restrict__ b1)
{
    extern __shared__ float xs[];
    __shared__ unsigned short list[1024];
    __shared__ int cnt;

    const int b   = blockIdx.x;
    const int tid = threadIdx.x;
    if (tid == 0) cnt = 0;
    __syncthreads();

    for (int h = tid; h < NHID; h += 256) {
        if ((g_flag[b * 32 + (h >> 5)] >> (h & 31)) & 1u) {
            const int idx = atomicAdd(&cnt, 1);
            list[idx] = (unsigned short)h;
        }
    }
    __syncthreads();

    const int nf = cnt;
    if (nf == 0) return;

    for (int i = tid; i < NUM_STEPS * NIN; i += 256) {
        const int t = i / NIN, k = i - t * NIN;
        xs[t * XLD + k] = X[((size_t)t * BATCH + b) * NIN + k];
    }
    __syncthreads();

    const int warpid = tid >> 5;
    const int lane   = tid & 31;

    for (int u = warpid; u < nf; u += 8) {
        const int h = (int)list[u];
        const float* wrow = W1 + (size_t)h * NIN;

        float dotv = 0.f;
        if (lane < NUM_STEPS) {
            const float* xr = xs + lane * XLD;
            float acc = 0.f;
#pragma unroll 8
            for (int k = 0; k < NIN; k++)
                acc = __fadd_rn(acc, __fmul_rn(xr[k], __ldg(wrow + k)));
            dotv = __fadd_rn(acc, __ldg(&b1[h]));
        }

        float mem = 0.f;
        uint32_t myspk = 0;
#pragma unroll
        for (int t = 0; t < NUM_STEPS; t++) {
            const float c = __shfl_sync(0xffffffffu, dotv, t);
            const float rst = (mem > THRESH) ? THRESH : 0.f;
            mem = __fsub_rn(__fadd_rn(__fmul_rn(BETA, mem), c), rst);
            if (lane == t) myspk = (mem > THRESH) ? 1u : 0u;
        }

        if (lane < NUM_STEPS) {
            uint32_t* wp = &g_maskT[(size_t)(h >> 5) * MTOT +
                                    (size_t)lane * BATCH + b];
            const uint32_t bit = 1u << (h & 31);
            if (myspk) atomicOr(wp, bit);
            else       atomicAnd(wp, ~bit);
        }
    }
}

// ---------------------------------------------------------------------------
// gemm2 (sparse-exact): cur2 = spk1 @ W2^T + b2. Skipping zero bits is
// bit-exact (rn(acc + rn(0*w)) == acc, incl. signed zeros since acc starts
// +0 and +0 + -0 = +0 in RN). Ascending-h order preserved. o-major smem
// (stride 1024) -> conflict-free per-o loads.
// ---------------------------------------------------------------------------
__global__ void __launch_bounds__(256)
gemm2_kernel(const float* __restrict__ W2, const float* __restrict__ b2)
{
    __shared__ float W2t[NOUT * 1024];   // [o][h]
    for (int i = threadIdx.x; i < NOUT * 1024; i += 256) {
        const int o = i >> 10, h = i & 1023;
        W2t[i] = (h < NHID) ? W2[o * NHID + h] : 0.f;
    }
    __syncthreads();

    const int row = blockIdx.x * 256 + threadIdx.x;

    float acc[NOUT];
#pragma unroll
    for (int o = 0; o < NOUT; o++) acc[o] = 0.f;

#pragma unroll 1
    for (int wd = 0; wd < 32; wd++) {
        uint32_t w = g_maskT[(size_t)wd * MTOT + row];
        while (w) {
            const int bit = __ffs(w) - 1;
            w &= w - 1;
            const int h = wd * 32 + bit;
#pragma unroll
            for (int o = 0; o < NOUT; o++)
                acc[o] = __fadd_rn(acc[o], W2t[o * 1024 + h]);
        }
    }

    float* out = g_cur2 + (size_t)row * NOUT;
#pragma unroll
    for (int o = 0; o < NOUT; o++)
        out[o] = __fadd_rn(acc[o], __ldg(&b2[o]));
}

// ---------------------------------------------------------------------------
// rec2: layer-2 recurrence + outputs [spk_rec | mem_rec].
// ---------------------------------------------------------------------------
__global__ void __launch_bounds__(256)
rec2_kernel(float* __restrict__ out)
{
    const int idx = blockIdx.x * blockDim.x + threadIdx.x;
    if (idx >= BATCH * NOUT) return;

    float mem = 0.f;
#pragma unroll
    for (int t = 0; t < NUM_STEPS; t++) {
        const float c   = g_cur2[(size_t)t * (BATCH * NOUT) + idx];
        const float rst = (mem > THRESH) ? THRESH : 0.f;
        mem = __fsub_rn(__fadd_rn(__fmul_rn(BETA, mem), c), rst);
        const float spk = (mem > THRESH) ? 1.f : 0.f;
        out[(size_t)t * (BATCH * NOUT) + idx] = spk;
        out[(size_t)NUM_STEPS * BATCH * NOUT + (size_t)t * (BATCH * NOUT) + idx] = mem;
    }
}

// ---------------------------------------------------------------------------
extern "C" void kernel_launch(void* const* d_in, const int* in_sizes, int n_in,
                              void* d_out, int out_size)
{
    const float* x  = (const float*)d_in[0];
    const float* W1 = (const float*)d_in[1];
    const float* b1 = (const float*)d_in[2];
    const float* W2 = (const float*)d_in[3];
    const float* b2 = (const float*)d_in[4];
    float* out = (float*)d_out;

    cudaFuncSetAttribute(gemm1t_kernel,
                         cudaFuncAttributeMaxDynamicSharedMemorySize,
                         STAGES * STAGE_BYTES);
    const int xs_bytes = NUM_STEPS * XLD * (int)sizeof(float);
    cudaFuncSetAttribute(fixup_kernel,
                         cudaFuncAttributeMaxDynamicSharedMemorySize, xs_bytes);

    splitx_kernel<<<(MTOT * 196) / 256, 256>>>(x);
    splitw_kernel<<<(1024 * 196) / 256, 256>>>(W1);

    dim3 g1(8, MTOT / 128);
    gemm1t_kernel<<<g1, 256, STAGES * STAGE_BYTES>>>(b1);

    flagrec_kernel<<<(BATCH * 32) / 8, 256>>>();

    fixup_kernel<<<BATCH, 256, xs_bytes>>>(x, W1, b1);

    gemm2_kernel<<<MTOT / 256, 256>>>(W2, b2);

    rec2_kernel<<<(BATCH * NOUT + 255) / 256, 256>>>(out);
}

// round 16
// speedup vs baseline: 1.1430x; 1.1430x over previous
#include <cuda_runtime.h>
#include <cuda_fp16.h>
#include <stdint.h>

// Problem constants
#define NUM_STEPS 25
#define BATCH     4096
#define NIN       784
#define NHID      1000
#define NOUT      10
#define MTOT      (NUM_STEPS * BATCH)   // 102400
#define BETA      0.95f
#define THRESH    1.0f

// Flag window per step (validated round 13).
#define DELTA 5e-5f

// Scratch (device globals; no runtime allocation allowed)
__device__ float     g_cur1[(size_t)MTOT * NHID];
__device__ uint32_t  g_maskT[(size_t)32 * MTOT];    // spk1 bits, [word][t*B+b]
__device__ float     g_cur2[(size_t)MTOT * NOUT];
__device__ uint32_t  g_flag[BATCH * 32];
__device__ __half    g_xh[(size_t)MTOT * NIN];
__device__ __half    g_xl[(size_t)MTOT * NIN];
__device__ __half    g_wh[(size_t)1024 * NIN];
__device__ __half    g_wl[(size_t)1024 * NIN];

static __device__ __forceinline__ uint32_t smem_u32(const void* p) {
    uint32_t a;
    asm("{ .reg .u64 t; cvta.to.shared.u64 t, %1; cvt.u32.u64 %0, t; }"
        : "=r"(a) : "l"(p));
    return a;
}

#define LDMX4(r0, r1, r2, r3, a) \
    asm volatile("ldmatrix.sync.aligned.m8n8.x4.shared.b16 {%0,%1,%2,%3}, [%4];" \
                 : "=r"(r0), "=r"(r1), "=r"(r2), "=r"(r3) : "r"(a))

#define MMA_F16(c, a, b) \
    asm volatile("mma.sync.aligned.m16n8k16.row.col.f32.f16.f16.f32 " \
                 "{%0,%1,%2,%3}, {%4,%5,%6,%7}, {%8,%9}, {%0,%1,%2,%3};" \
                 : "+f"((c)[0]), "+f"((c)[1]), "+f"((c)[2]), "+f"((c)[3]) \
                 : "r"((a)[0]), "r"((a)[1]), "r"((a)[2]), "r"((a)[3]), \
                   "r"((b)[0]), "r"((b)[1]))

// ---------------------------------------------------------------------------
// Split kernels (vectorized): v = vh + vl (fp16 hi + fp16 residual).
// ---------------------------------------------------------------------------
__global__ void __launch_bounds__(256)
splitx_kernel(const float* __restrict__ X)
{
    const int id = blockIdx.x * 256 + threadIdx.x;   // < MTOT*196
    const int m  = id / 196;
    const int k  = (id - m * 196) * 4;
    const float4 v = *(const float4*)(X + (size_t)m * NIN + k);
    __half h0 = __float2half_rn(v.x), h1 = __float2half_rn(v.y);
    __half h2 = __float2half_rn(v.z), h3 = __float2half_rn(v.w);
    __half l0 = __float2half_rn(v.x - __half2float(h0));
    __half l1 = __float2half_rn(v.y - __half2float(h1));
    __half l2 = __float2half_rn(v.z - __half2float(h2));
    __half l3 = __float2half_rn(v.w - __half2float(h3));
    __half2 hh[2] = {__halves2half2(h0, h1), __halves2half2(h2, h3)};
    __half2 ll[2] = {__halves2half2(l0, l1), __halves2half2(l2, l3)};
    *(uint2*)(g_xh + (size_t)m * NIN + k) = *(uint2*)hh;
    *(uint2*)(g_xl + (size_t)m * NIN + k) = *(uint2*)ll;
}

__global__ void __launch_bounds__(256)
splitw_kernel(const float* __restrict__ W1)
{
    const int id = blockIdx.x * 256 + threadIdx.x;   // < 1024*196
    const int h  = id / 196;
    const int k  = (id - h * 196) * 4;
    float4 v = make_float4(0.f, 0.f, 0.f, 0.f);
    if (h < NHID) v = *(const float4*)(W1 + (size_t)h * NIN + k);
    __half h0 = __float2half_rn(v.x), h1 = __float2half_rn(v.y);
    __half h2 = __float2half_rn(v.z), h3 = __float2half_rn(v.w);
    __half l0 = __float2half_rn(v.x - __half2float(h0));
    __half l1 = __float2half_rn(v.y - __half2float(h1));
    __half l2 = __float2half_rn(v.z - __half2float(h2));
    __half l3 = __float2half_rn(v.w - __half2float(h3));
    __half2 hh[2] = {__halves2half2(h0, h1), __halves2half2(h2, h3)};
    __half2 ll[2] = {__halves2half2(l0, l1), __halves2half2(l2, l3)};
    *(uint2*)(g_wh + (size_t)h * NIN + k) = *(uint2*)hh;
    *(uint2*)(g_wl + (size_t)h * NIN + k) = *(uint2*)ll;
}

// ---------------------------------------------------------------------------
// gemm1 on HMMA fp16 (ROUND-13 PROVEN VERSION): cur1 ~= Xh@Wh^T + Xh@Wl^T
// + Xl@Wh^T + b1. CTA tile 128x128, 8 warps (2x4), warp tile 64x32, 49 k-steps
// of 16. Double-buffered static smem, register prefetch, one sync per step.
// ---------------------------------------------------------------------------
#define TILE_BYTES 6144        // 128 * 48
#define STAGE_BYTES 24576
#define NKS 49

__global__ void __launch_bounds__(256)
gemm1t_kernel(const float* __restrict__ b1)
{
    __shared__ __align__(16) char smem[2][STAGE_BYTES];

    const int tid    = threadIdx.x;
    const int wid    = tid >> 5;
    const int lane   = tid & 31;
    const int bm     = blockIdx.y * 128;
    const int bn     = blockIdx.x * 128;
    const int warp_m = (wid >> 2) * 64;
    const int warp_n = (wid & 3) * 32;

    const int lrow = tid >> 1;
    const int lc   = tid & 1;
    const __half* gxh = g_xh + (size_t)(bm + lrow) * NIN + lc * 8;
    const __half* gxl = g_xl + (size_t)(bm + lrow) * NIN + lc * 8;
    const __half* gwh = g_wh + (size_t)(bn + lrow) * NIN + lc * 8;
    const __half* gwl = g_wl + (size_t)(bn + lrow) * NIN + lc * 8;
    const int soff = lrow * 48 + lc * 16;

    const uint32_t sb = smem_u32(smem);
    const uint32_t aoff = (uint32_t)((warp_m + (lane & 15)) * 48 + (lane >> 4) * 16);
    const uint32_t boff0 = (uint32_t)((warp_n + ((lane >> 4) << 3) + (lane & 7)) * 48
                                      + ((lane >> 3) & 1) * 16);
    const uint32_t boff1 = boff0 + 16 * 48;

    float acc[4][4][4];
#pragma unroll
    for (int i = 0; i < 4; i++)
#pragma unroll
        for (int j = 0; j < 4; j++)
#pragma unroll
            for (int r = 0; r < 4; r++) acc[i][j][r] = 0.f;

    uint4 p0, p1, p2, p3;
    p0 = *(const uint4*)(gxh);
    p1 = *(const uint4*)(gxl);
    p2 = *(const uint4*)(gwh);
    p3 = *(const uint4*)(gwl);
    {
        char* s = smem[0] + soff;
        *(uint4*)(s)                  = p0;
        *(uint4*)(s + TILE_BYTES)     = p1;
        *(uint4*)(s + 2 * TILE_BYTES) = p2;
        *(uint4*)(s + 3 * TILE_BYTES) = p3;
    }
    __syncthreads();

#pragma unroll 1
    for (int kt = 0; kt < NKS; kt++) {
        const int cur = kt & 1;

        if (kt + 1 < NKS) {
            const int ko = (kt + 1) * 16;
            p0 = *(const uint4*)(gxh + ko);
            p1 = *(const uint4*)(gxl + ko);
            p2 = *(const uint4*)(gwh + ko);
            p3 = *(const uint4*)(gwl + ko);
        }

        const uint32_t st = sb + (uint32_t)cur * STAGE_BYTES;

        uint32_t bh[8], bl[8];
        LDMX4(bh[0], bh[1], bh[2], bh[3], st + 2 * TILE_BYTES + boff0);
        LDMX4(bh[4], bh[5], bh[6], bh[7], st + 2 * TILE_BYTES + boff1);
        LDMX4(bl[0], bl[1], bl[2], bl[3], st + 3 * TILE_BYTES + boff0);
        LDMX4(bl[4], bl[5], bl[6], bl[7], st + 3 * TILE_BYTES + boff1);

#pragma unroll
        for (int mi = 0; mi < 4; mi++) {
            uint32_t ah[4], al[4];
            LDMX4(ah[0], ah[1], ah[2], ah[3], st + aoff + mi * (16 * 48));
            LDMX4(al[0], al[1], al[2], al[3], st + TILE_BYTES + aoff + mi * (16 * 48));
#pragma unroll
            for (int nj = 0; nj < 4; nj++) {
                uint32_t bhf[2] = {bh[nj * 2], bh[nj * 2 + 1]};
                uint32_t blf[2] = {bl[nj * 2], bl[nj * 2 + 1]};
                MMA_F16(acc[mi][nj], ah, bhf);   // hh
                MMA_F16(acc[mi][nj], ah, blf);   // hl
                MMA_F16(acc[mi][nj], al, bhf);   // lh
            }
        }

        if (kt + 1 < NKS) {
            char* s = smem[(kt + 1) & 1] + soff;
            *(uint4*)(s)                  = p0;
            *(uint4*)(s + TILE_BYTES)     = p1;
            *(uint4*)(s + 2 * TILE_BYTES) = p2;
            *(uint4*)(s + 3 * TILE_BYTES) = p3;
            __syncthreads();
        }
    }

    const int m0 = bm + warp_m + (lane >> 2);
    const int n0 = bn + warp_n + (lane & 3) * 2;
#pragma unroll
    for (int mi = 0; mi < 4; mi++) {
#pragma unroll
        for (int nj = 0; nj < 4; nj++) {
            const int n = n0 + nj * 8;
            if (n < NHID - 1) {
                const float bx = __ldg(&b1[n]);
                const float by = __ldg(&b1[n + 1]);
                const int mA = m0 + mi * 16;
                float2 v0, v1;
                v0.x = __fadd_rn(acc[mi][nj][0], bx);
                v0.y = __fadd_rn(acc[mi][nj][1], by);
                v1.x = __fadd_rn(acc[mi][nj][2], bx);
                v1.y = __fadd_rn(acc[mi][nj][3], by);
                *(float2*)&g_cur1[(size_t)mA * NHID + n] = v0;
                *(float2*)&g_cur1[(size_t)(mA + 8) * NHID + n] = v1;
            }
        }
    }
}

// ---------------------------------------------------------------------------
// flagrec: preload all 25 cur1 values (MLP=25), then recurrence with error
// radius; writes provisional spike mask + per-chain flag bits.
// ---------------------------------------------------------------------------
__global__ void __launch_bounds__(256)
flagrec_kernel()
{
    const int warp  = (blockIdx.x * blockDim.x + threadIdx.x) >> 5;
    const int lane  = threadIdx.x & 31;
    const int chunk = warp & 31;
    const int b     = warp >> 5;
    if (b >= BATCH) return;

    const int h = chunk * 32 + lane;
    const bool valid = (h < NHID);

    float cbuf[NUM_STEPS];
#pragma unroll
    for (int t = 0; t < NUM_STEPS; t++)
        cbuf[t] = valid ? g_cur1[((size_t)t * BATCH + b) * NHID + h] : -1.f;

    float mem = 0.f, e = 0.f;
    bool flg = false;
#pragma unroll
    for (int t = 0; t < NUM_STEPS; t++) {
        const float c = cbuf[t];
        const float rst = (mem > THRESH) ? THRESH : 0.f;
        mem = __fsub_rn(__fadd_rn(__fmul_rn(BETA, mem), c), rst);
        e = BETA * e + DELTA + 2e-7f * (fabsf(mem) + 2.f);
        flg = flg || (valid && fabsf(mem - THRESH) <= e);
        const uint32_t w = __ballot_sync(0xffffffffu, mem > THRESH);
        if (lane == 0)
            g_maskT[(size_t)chunk * MTOT + (size_t)t * BATCH + b] = w;
    }
    const uint32_t f = __ballot_sync(0xffffffffu, flg);
    if (lane == 0) g_flag[b * 32 + chunk] = f;
}

// ---------------------------------------------------------------------------
// Fixup: exact unfused chain for flagged (b,h); patch mask bits atomically.
// ---------------------------------------------------------------------------
#define XLD 785

__global__ void __launch_bounds__(256)
fixup_kernel(const float* __restrict__ X, const float* __restrict__ W1,
             const float* __restrict__ b1)
{
    extern __shared__ float xs[];
    __shared__ unsigned short list[1024];
    __shared__ int cnt;

    const int b   = blockIdx.x;
    const int tid = threadIdx.x;
    if (tid == 0) cnt = 0;
    __syncthreads();

    for (int h = tid; h < NHID; h += 256) {
        if ((g_flag[b * 32 + (h >> 5)] >> (h & 31)) & 1u) {
            const int idx = atomicAdd(&cnt, 1);
            list[idx] = (unsigned short)h;
        }
    }
    __syncthreads();

    const int nf = cnt;
    if (nf == 0) return;

    for (int i = tid; i < NUM_STEPS * NIN; i += 256) {
        const int t = i / NIN, k = i - t * NIN;
        xs[t * XLD + k] = X[((size_t)t * BATCH + b) * NIN + k];
    }
    __syncthreads();

    const int warpid = tid >> 5;
    const int lane   = tid & 31;

    for (int u = warpid; u < nf; u += 8) {
        const int h = (int)list[u];
        const float* wrow = W1 + (size_t)h * NIN;

        float dotv = 0.f;
        if (lane < NUM_STEPS) {
            const float* xr = xs + lane * XLD;
            float acc = 0.f;
#pragma unroll 8
            for (int k = 0; k < NIN; k++)
                acc = __fadd_rn(acc, __fmul_rn(xr[k], __ldg(wrow + k)));
            dotv = __fadd_rn(acc, __ldg(&b1[h]));
        }

        float mem = 0.f;
        uint32_t myspk = 0;
#pragma unroll
        for (int t = 0; t < NUM_STEPS; t++) {
            const float c = __shfl_sync(0xffffffffu, dotv, t);
            const float rst = (mem > THRESH) ? THRESH : 0.f;
            mem = __fsub_rn(__fadd_rn(__fmul_rn(BETA, mem), c), rst);
            if (lane == t) myspk = (mem > THRESH) ? 1u : 0u;
        }

        if (lane < NUM_STEPS) {
            uint32_t* wp = &g_maskT[(size_t)(h >> 5) * MTOT +
                                    (size_t)lane * BATCH + b];
            const uint32_t bit = 1u << (h & 31);
            if (myspk) atomicOr(wp, bit);
            else       atomicAnd(wp, ~bit);
        }
    }
}

// ---------------------------------------------------------------------------
// gemm2 (sparse-exact): cur2 = spk1 @ W2^T + b2. Skipping zero bits is
// bit-exact; ascending-h order preserved; o-major smem -> conflict-free.
// ---------------------------------------------------------------------------
__global__ void __launch_bounds__(256)
gemm2_kernel(const float* __restrict__ W2, const float* __restrict__ b2)
{
    __shared__ float W2t[NOUT * 1024];   // [o][h]
    for (int i = threadIdx.x; i < NOUT * 1024; i += 256) {
        const int o = i >> 10, h = i & 1023;
        W2t[i] = (h < NHID) ? W2[o * NHID + h] : 0.f;
    }
    __syncthreads();

    const int row = blockIdx.x * 256 + threadIdx.x;

    float acc[NOUT];
#pragma unroll
    for (int o = 0; o < NOUT; o++) acc[o] = 0.f;

#pragma unroll 1
    for (int wd = 0; wd < 32; wd++) {
        uint32_t w = g_maskT[(size_t)wd * MTOT + row];
        while (w) {
            const int bit = __ffs(w) - 1;
            w &= w - 1;
            const int h = wd * 32 + bit;
#pragma unroll
            for (int o = 0; o < NOUT; o++)
                acc[o] = __fadd_rn(acc[o], W2t[o * 1024 + h]);
        }
    }

    float* out = g_cur2 + (size_t)row * NOUT;
#pragma unroll
    for (int o = 0; o < NOUT; o++)
        out[o] = __fadd_rn(acc[o], __ldg(&b2[o]));
}

// ---------------------------------------------------------------------------
// rec2: layer-2 recurrence + outputs [spk_rec | mem_rec].
// ---------------------------------------------------------------------------
__global__ void __launch_bounds__(256)
rec2_kernel(float* __restrict__ out)
{
    const int idx = blockIdx.x * blockDim.x + threadIdx.x;
    if (idx >= BATCH * NOUT) return;

    float mem = 0.f;
#pragma unroll
    for (int t = 0; t < NUM_STEPS; t++) {
        const float c   = g_cur2[(size_t)t * (BATCH * NOUT) + idx];
        const float rst = (mem > THRESH) ? THRESH : 0.f;
        mem = __fsub_rn(__fadd_rn(__fmul_rn(BETA, mem), c), rst);
        const float spk = (mem > THRESH) ? 1.f : 0.f;
        out[(size_t)t * (BATCH * NOUT) + idx] = spk;
        out[(size_t)NUM_STEPS * BATCH * NOUT + (size_t)t * (BATCH * NOUT) + idx] = mem;
    }
}

// ---------------------------------------------------------------------------
extern "C" void kernel_launch(void* const* d_in, const int* in_sizes, int n_in,
                              void* d_out, int out_size)
{
    const float* x  = (const float*)d_in[0];
    const float* W1 = (const float*)d_in[1];
    const float* b1 = (const float*)d_in[2];
    const float* W2 = (const float*)d_in[3];
    const float* b2 = (const float*)d_in[4];
    float* out = (float*)d_out;

    const int xs_bytes = NUM_STEPS * XLD * (int)sizeof(float);
    cudaFuncSetAttribute(fixup_kernel,
                         cudaFuncAttributeMaxDynamicSharedMemorySize, xs_bytes);

    splitx_kernel<<<(MTOT * 196) / 256, 256>>>(x);
    splitw_kernel<<<(1024 * 196) / 256, 256>>>(W1);

    dim3 g1(8, MTOT / 128);
    gemm1t_kernel<<<g1, 256>>>(b1);

    flagrec_kernel<<<(BATCH * 32) / 8, 256>>>();

    fixup_kernel<<<BATCH, 256, xs_bytes>>>(x, W1, b1);

    gemm2_kernel<<<MTOT / 256, 256>>>(W2, b2);

    rec2_kernel<<<(BATCH * NOUT + 255) / 256, 256>>>(out);
}